// round 5
// baseline (speedup 1.0000x reference)
#include <cuda_runtime.h>
#include <cuda_bf16.h>

#define CH 256
#define CW 256
#define NS 64          // curve samples
#define NB 16          // batch
#define RPB 8          // rows per block
#define NPAIR (RPB/2)
#define EPSF 1e-6f

struct P2 { float y, x; };

// Precomputed arc-length-uniform samples: [batch][sample] = (x, y)
__device__ float2 g_samples[NB * NS];

// ---- packed f32x2 helpers (Blackwell FFMA2 path, PTX-only) ----
__device__ __forceinline__ unsigned long long pk2(float a, float b) {
    unsigned long long r;
    asm("mov.b64 %0, {%1, %2};" : "=l"(r) : "f"(a), "f"(b));
    return r;
}
__device__ __forceinline__ void upk2(unsigned long long v, float& a, float& b) {
    asm("mov.b64 {%0, %1}, %2;" : "=f"(a), "=f"(b) : "l"(v));
}
__device__ __forceinline__ unsigned long long fma2(unsigned long long a,
                                                   unsigned long long b,
                                                   unsigned long long c) {
    unsigned long long r;
    asm("fma.rn.f32x2 %0, %1, %2, %3;" : "=l"(r) : "l"(a), "l"(b), "l"(c));
    return r;
}
__device__ __forceinline__ unsigned long long add2(unsigned long long a,
                                                   unsigned long long b) {
    unsigned long long r;
    asm("add.rn.f32x2 %0, %1, %2;" : "=l"(r) : "l"(a), "l"(b));
    return r;
}

__device__ __forceinline__ P2 bez4(P2 c0, P2 c1, P2 c2, P2 c3, float t) {
    float s = 1.0f - t;
    P2 a{ s*c0.y + t*c1.y, s*c0.x + t*c1.x };
    P2 b{ s*c1.y + t*c2.y, s*c1.x + t*c2.x };
    P2 c{ s*c2.y + t*c3.y, s*c2.x + t*c3.x };
    P2 d{ s*a.y  + t*b.y , s*a.x  + t*b.x  };
    P2 e{ s*b.y  + t*c.y , s*b.x  + t*c.x  };
    return P2{ s*d.y + t*e.y, s*d.x + t*e.x };
}

// ==================== Kernel 1: curve sampling (once per batch) ====================
__global__ __launch_bounds__(NS) void sample_kernel(const float* __restrict__ inputs)
{
    __shared__ float s_y[NS], s_x[NS];
    __shared__ float s_cum[NS];

    const int tid = threadIdx.x;     // 0..63
    const int b   = blockIdx.x;

    P2 c0{ inputs[b*8+0]*256.0f, inputs[b*8+1]*256.0f };
    P2 c1{ inputs[b*8+2]*256.0f, inputs[b*8+3]*256.0f };
    P2 c2{ inputs[b*8+4]*256.0f, inputs[b*8+5]*256.0f };
    P2 c3{ inputs[b*8+6]*256.0f, inputs[b*8+7]*256.0f };

    const float inv63 = 1.0f / 63.0f;

    // Phase A: coarse samples at ts0 = linspace(0,1,64)
    {
        float t = (float)tid * inv63;
        P2 p = bez4(c0, c1, c2, c3, t);
        s_y[tid] = p.y; s_x[tid] = p.x;
    }
    __syncthreads();

    // Phase B: segment lengths
    {
        float c = 0.0f;
        if (tid > 0) {
            float dy = s_y[tid] - s_y[tid-1];
            float dx = s_x[tid] - s_x[tid-1];
            c = sqrtf(dy*dy + dx*dx);
        }
        s_cum[tid] = c;
    }
    __syncthreads();

    // Phase C: inclusive scan (Hillis-Steele)
    #pragma unroll
    for (int off = 1; off < NS; off <<= 1) {
        float v = 0.0f;
        if (tid >= off) v = s_cum[tid - off];
        __syncthreads();
        s_cum[tid] += v;
        __syncthreads();
    }

    float total = s_cum[NS-1];
    __syncthreads();
    float rnorm = 1.0f / (total + EPSF);
    s_cum[tid] *= rnorm;
    __syncthreads();

    // Phase D: t_arc = interp(ts0, u, ts0), final samples -> global
    {
        float xq = (float)tid * inv63;
        int cnt = 0;
        #pragma unroll
        for (int k = 0; k < NS; k++) cnt += (s_cum[k] <= xq) ? 1 : 0;
        int iss = cnt; if (iss < 1) iss = 1; if (iss > NS-1) iss = NS-1;
        int j = iss - 1;
        float uj  = s_cum[j];
        float uj1 = s_cum[j+1];
        float tj  = (float)j * inv63;
        float tnew = tj + (xq - uj) * (inv63 / (uj1 - uj));
        if (xq > s_cum[NS-1]) tnew = 1.0f;
        P2 p = bez4(c0, c1, c2, c3, tnew);
        g_samples[b * NS + tid] = make_float2(p.x, p.y);   // (x, y)
    }
}

// ==================== Kernel 2: rasterization ====================
__global__ __launch_bounds__(256) void pixel_kernel(
    const float* __restrict__ widths,
    const float* __restrict__ aas,
    float* __restrict__ out)
{
    __shared__ float2 s_s[NS];           // .x = x-coord, .y = y-coord

    const int tid = threadIdx.x;
    const int b   = blockIdx.y;
    const int r0  = blockIdx.x * RPB;

    if (tid < NS) s_s[tid] = g_samples[b * NS + tid];
    __syncthreads();

    // ---- per-warp spatial cull: 32-col x 8-row region ----
    const int lane = tid & 31;
    const int wc0  = tid & ~31;
    const float w  = widths[b];

    {
        const float ccx = (float)wc0 + 15.5f;
        const float ccy = (float)r0  + 3.5f;
        float m2 = 3.0e38f;
        #pragma unroll
        for (int k = 0; k < 2; k++) {
            float2 sv = s_s[lane + 32*k];
            float ax = fmaxf(fabsf(sv.x - ccx) - 15.5f, 0.0f);
            float ay = fmaxf(fabsf(sv.y - ccy) - 3.5f,  0.0f);
            m2 = fminf(m2, fmaf(ax, ax, ay*ay));
        }
        #pragma unroll
        for (int off = 16; off > 0; off >>= 1)
            m2 = fminf(m2, __shfl_xor_sync(0xffffffffu, m2, off));

        if (m2 >= w * w) {
            float* orow = out + ((size_t)b * CH + r0) * CW + tid;
            #pragma unroll
            for (int i = 0; i < RPB; i++) orow[(size_t)i * CW] = 0.0f;
            return;
        }
    }

    // ---- min squared distance; thread = column, RPB rows, packed x2 ----
    float minv[RPB];
    #pragma unroll
    for (int i = 0; i < RPB; i++) minv[i] = 3.0e38f;

    const float px  = (float)tid;
    const float fr0 = (float)r0;

    unsigned long long cpair[NPAIR];
    #pragma unroll
    for (int j = 0; j < NPAIR; j++)
        cpair[j] = pk2(-fr0 - (float)(2*j), -fr0 - (float)(2*j + 1));

    #pragma unroll 16
    for (int s = 0; s < NS; s++) {
        float2 sv = s_s[s];
        float dx  = sv.x - px;
        float dx2 = dx * dx;
        unsigned long long dx2p = pk2(dx2, dx2);
        unsigned long long syp  = pk2(sv.y, sv.y);
        #pragma unroll
        for (int j = 0; j < NPAIR; j++) {
            unsigned long long dyp = add2(syp, cpair[j]);
            unsigned long long d2p = fma2(dyp, dyp, dx2p);
            float lo, hi;
            upk2(d2p, lo, hi);
            minv[2*j]     = fminf(minv[2*j],     lo);
            minv[2*j + 1] = fminf(minv[2*j + 1], hi);
        }
    }

    // ---- epilogue ----
    const float aa   = aas[b];
    const float invw = 1.0f / w;
    float* orow = out + ((size_t)b * CH + r0) * CW + tid;
    #pragma unroll
    for (int i = 0; i < RPB; i++) {
        float md  = sqrtf(minv[i]);
        float v   = __powf(md * invw + EPSF, aa);
        float res = 1.0f - v;
        res = fminf(fmaxf(res, 0.0f), 1.0f);
        orow[(size_t)i * CW] = res;
    }
}

extern "C" void kernel_launch(void* const* d_in, const int* in_sizes, int n_in,
                              void* d_out, int out_size) {
    const float* inputs = (const float*)d_in[0];
    const float* widths = (const float*)d_in[1];
    const float* aas    = (const float*)d_in[2];
    float* out = (float*)d_out;

    sample_kernel<<<NB, NS>>>(inputs);
    dim3 grid(CH / RPB, NB);
    pixel_kernel<<<grid, 256>>>(widths, aas, out);
}

// round 6
// speedup vs baseline: 1.2694x; 1.2694x over previous
#include <cuda_runtime.h>
#include <cuda_bf16.h>

#define CH 256
#define CW 256
#define NS 64          // curve samples
#define NB 16          // batch
#define RPB 8          // rows per block
#define NPAIR (RPB/2)
#define NWARP 8
#define EPSF 1e-6f

struct P2 { float y, x; };

// ---- packed f32x2 helpers (Blackwell FFMA2 path, PTX-only) ----
__device__ __forceinline__ unsigned long long pk2(float a, float b) {
    unsigned long long r;
    asm("mov.b64 %0, {%1, %2};" : "=l"(r) : "f"(a), "f"(b));
    return r;
}
__device__ __forceinline__ void upk2(unsigned long long v, float& a, float& b) {
    asm("mov.b64 {%0, %1}, %2;" : "=f"(a), "=f"(b) : "l"(v));
}
__device__ __forceinline__ unsigned long long fma2(unsigned long long a,
                                                   unsigned long long b,
                                                   unsigned long long c) {
    unsigned long long r;
    asm("fma.rn.f32x2 %0, %1, %2, %3;" : "=l"(r) : "l"(a), "l"(b), "l"(c));
    return r;
}
__device__ __forceinline__ unsigned long long add2(unsigned long long a,
                                                   unsigned long long b) {
    unsigned long long r;
    asm("add.rn.f32x2 %0, %1, %2;" : "=l"(r) : "l"(a), "l"(b));
    return r;
}

__device__ __forceinline__ P2 bez4(P2 c0, P2 c1, P2 c2, P2 c3, float t) {
    float s = 1.0f - t;
    P2 a{ s*c0.y + t*c1.y, s*c0.x + t*c1.x };
    P2 b{ s*c1.y + t*c2.y, s*c1.x + t*c2.x };
    P2 c{ s*c2.y + t*c3.y, s*c2.x + t*c3.x };
    P2 d{ s*a.y  + t*b.y , s*a.x  + t*b.x  };
    P2 e{ s*b.y  + t*c.y , s*b.x  + t*c.x  };
    return P2{ s*d.y + t*e.y, s*d.x + t*e.x };
}

__global__ __launch_bounds__(256) void curve_kernel(
    const float* __restrict__ inputs,   // [16,4,2] (y,x) in [0,1]
    const float* __restrict__ widths,   // [16]
    const float* __restrict__ aas,      // [16]
    float* __restrict__ out)            // [16,256,256]
{
    __shared__ float s_y[NS], s_x[NS];
    __shared__ float s_cum[NS];
    __shared__ float2 s_s[NS];                 // samples: .x = x, .y = y
    __shared__ float2 s_cand[NWARP][NS];       // per-warp candidate lists

    const int tid = threadIdx.x;
    const int b   = blockIdx.y;
    const int r0  = blockIdx.x * RPB;

    P2 c0{ inputs[b*8+0]*256.0f, inputs[b*8+1]*256.0f };
    P2 c1{ inputs[b*8+2]*256.0f, inputs[b*8+3]*256.0f };
    P2 c2{ inputs[b*8+4]*256.0f, inputs[b*8+5]*256.0f };
    P2 c3{ inputs[b*8+6]*256.0f, inputs[b*8+7]*256.0f };

    const float inv63 = 1.0f / 63.0f;

    // ---- Phase A: coarse samples at ts0 = linspace(0,1,64) ----
    if (tid < NS) {
        float t = (float)tid * inv63;
        P2 p = bez4(c0, c1, c2, c3, t);
        s_y[tid] = p.y; s_x[tid] = p.x;
    }
    __syncthreads();

    // ---- Phase B: segment lengths ----
    if (tid < NS) {
        float c = 0.0f;
        if (tid > 0) {
            float dy = s_y[tid] - s_y[tid-1];
            float dx = s_x[tid] - s_x[tid-1];
            c = sqrtf(dy*dy + dx*dx);
        }
        s_cum[tid] = c;
    }
    __syncthreads();

    // ---- Phase C: inclusive scan (Hillis-Steele) ----
    #pragma unroll
    for (int off = 1; off < NS; off <<= 1) {
        float v = 0.0f;
        if (tid < NS && tid >= off) v = s_cum[tid - off];
        __syncthreads();
        if (tid < NS) s_cum[tid] += v;
        __syncthreads();
    }

    float total = s_cum[NS-1];
    __syncthreads();
    float rnorm = 1.0f / (total + EPSF);
    if (tid < NS) s_cum[tid] *= rnorm;
    __syncthreads();

    // ---- Phase D: t_arc = interp(ts0, u, ts0), then final samples ----
    if (tid < NS) {
        float xq = (float)tid * inv63;
        int cnt = 0;
        #pragma unroll
        for (int k = 0; k < NS; k++) cnt += (s_cum[k] <= xq) ? 1 : 0;
        int iss = cnt; if (iss < 1) iss = 1; if (iss > NS-1) iss = NS-1;
        int j = iss - 1;
        float uj  = s_cum[j];
        float uj1 = s_cum[j+1];
        float tj  = (float)j * inv63;
        float tnew = tj + (xq - uj) * (inv63 / (uj1 - uj));
        if (xq > s_cum[NS-1]) tnew = 1.0f;
        P2 p = bez4(c0, c1, c2, c3, tnew);
        s_s[tid] = make_float2(p.x, p.y);      // (x, y)
    }
    __syncthreads();

    // ================= Per-warp candidate build =================
    // Warp region: columns [wc0, wc0+31], rows [r0, r0+7].
    // Sample is a candidate iff its distance lower bound to the region < w.
    // Pixels' true min-dist < w can only come from candidates, so iterating
    // candidates with minv clamped at w^2 is exact.
    const int lane = tid & 31;
    const int wid  = tid >> 5;
    const int wc0  = tid & ~31;
    const float w  = widths[b];
    const float w2 = w * w;

    int ccount = 0;
    {
        const float ccx = (float)wc0 + 15.5f;
        const float ccy = (float)r0  + 3.5f;
        #pragma unroll
        for (int k = 0; k < 2; k++) {
            float2 sv = s_s[lane + 32*k];
            float ax = fmaxf(fabsf(sv.x - ccx) - 15.5f, 0.0f);
            float ay = fmaxf(fabsf(sv.y - ccy) - 3.5f,  0.0f);
            float lb2 = fmaf(ax, ax, ay*ay);
            bool pred = lb2 < w2;
            unsigned mask = __ballot_sync(0xffffffffu, pred);
            int pos = __popc(mask & ((1u << lane) - 1u));
            if (pred) s_cand[wid][ccount + pos] = sv;
            ccount += __popc(mask);
        }
        __syncwarp();
    }

    float* orow = out + ((size_t)b * CH + r0) * CW + tid;

    if (ccount == 0) {
        // whole region provably >= w away -> exactly 0 (matches reference clip)
        #pragma unroll
        for (int i = 0; i < RPB; i++) orow[(size_t)i * CW] = 0.0f;
        return;
    }

    // ---- min squared distance over candidates; clamp at w^2 ----
    float minv[RPB];
    #pragma unroll
    for (int i = 0; i < RPB; i++) minv[i] = w2;

    const float px  = (float)tid;
    const float fr0 = (float)r0;

    unsigned long long cpair[NPAIR];
    #pragma unroll
    for (int j = 0; j < NPAIR; j++)
        cpair[j] = pk2(-fr0 - (float)(2*j), -fr0 - (float)(2*j + 1));

    #pragma unroll 4
    for (int s = 0; s < ccount; s++) {
        float2 sv = s_cand[wid][s];
        float dx  = sv.x - px;
        float dx2 = dx * dx;
        unsigned long long dx2p = pk2(dx2, dx2);
        unsigned long long syp  = pk2(sv.y, sv.y);
        #pragma unroll
        for (int j = 0; j < NPAIR; j++) {
            unsigned long long dyp = add2(syp, cpair[j]);
            unsigned long long d2p = fma2(dyp, dyp, dx2p);
            float lo, hi;
            upk2(d2p, lo, hi);
            minv[2*j]     = fminf(minv[2*j],     lo);
            minv[2*j + 1] = fminf(minv[2*j + 1], hi);
        }
    }

    // ---- epilogue ----
    const float aa   = aas[b];
    const float invw = 1.0f / w;
    #pragma unroll
    for (int i = 0; i < RPB; i++) {
        float md  = sqrtf(minv[i]);
        float v   = __powf(md * invw + EPSF, aa);
        float res = 1.0f - v;
        res = fminf(fmaxf(res, 0.0f), 1.0f);
        orow[(size_t)i * CW] = res;
    }
}

extern "C" void kernel_launch(void* const* d_in, const int* in_sizes, int n_in,
                              void* d_out, int out_size) {
    const float* inputs = (const float*)d_in[0];
    const float* widths = (const float*)d_in[1];
    const float* aas    = (const float*)d_in[2];
    float* out = (float*)d_out;
    dim3 grid(CH / RPB, NB);
    curve_kernel<<<grid, 256>>>(inputs, widths, aas, out);
}